// round 5
// baseline (speedup 1.0000x reference)
#include <cuda_runtime.h>
#include <cstdint>

#define Bb   32
#define Tt   2048
#define Hh   256
#define G3   768
#define NVv  18
#define NOo  17
#define CL   4       // CTAs per cluster
#define NT   416     // 12 GEMM warps + 1 epilogue warp
#define NGT  384     // GEMM threads

__device__ float g_hout[Bb * Tt * Hh];

// ---------------- helpers ----------------
__device__ __forceinline__ unsigned smem_u32(const void* p) {
    return (unsigned)__cvta_generic_to_shared(p);
}
__device__ __forceinline__ unsigned mapa_u32(unsigned local, int rank) {
    unsigned r;
    asm("mapa.shared::cluster.u32 %0, %1, %2;" : "=r"(r) : "r"(local), "r"(rank));
    return r;
}
__device__ __forceinline__ unsigned long long pack2(float lo, float hi) {
    unsigned long long v;
    asm("mov.b64 %0, {%1, %2};" : "=l"(v) : "f"(lo), "f"(hi));
    return v;
}
__device__ __forceinline__ float2 unpack2(unsigned long long v) {
    float lo, hi;
    asm("mov.b64 {%0, %1}, %2;" : "=f"(lo), "=f"(hi) : "l"(v));
    return make_float2(lo, hi);
}
__device__ __forceinline__ unsigned long long fma2(unsigned long long a,
                                                   unsigned long long b,
                                                   unsigned long long c) {
    unsigned long long d;
    asm("fma.rn.f32x2 %0, %1, %2, %3;" : "=l"(d) : "l"(a), "l"(b), "l"(c));
    return d;
}
__device__ __forceinline__ float fast_sigmoid(float x) {
    float e;
    asm("ex2.approx.f32 %0, %1;" : "=f"(e) : "f"(-1.4426950408889634f * x));
    float r;
    asm("rcp.approx.f32 %0, %1;" : "=f"(r) : "f"(1.0f + e));
    return r;
}
__device__ __forceinline__ float fast_tanh(float x) {
    return fmaf(2.0f, fast_sigmoid(2.0f * x), -1.0f);
}
__device__ __forceinline__ void mbar_arm(unsigned m, unsigned bytes) {
    asm volatile("mbarrier.arrive.expect_tx.shared.b64 _, [%0], %1;"
                 :: "r"(m), "r"(bytes) : "memory");
}
__device__ __forceinline__ void mbar_wait(unsigned m, unsigned par) {
    unsigned done;
    do {
        asm volatile(
            "{\n\t.reg .pred P;\n\t"
            "mbarrier.try_wait.parity.acquire.cluster.shared::cta.b64 P, [%1], %2, 0x989680;\n\t"
            "selp.b32 %0, 1, 0, P;\n\t}"
            : "=r"(done) : "r"(m), "r"(par) : "memory");
    } while (!done);
}
__device__ __forceinline__ void bar_arrive(int id) {
    asm volatile("bar.arrive %0, %1;" :: "r"(id), "r"(NT));
}
__device__ __forceinline__ void bar_wait(int id) {
    asm volatile("bar.sync %0, %1;" :: "r"(id), "r"(NT) : "memory");
}

// ---------------- kernel 1: GRU scan ----------------
// 16 clusters x 4 CTAs; each cluster runs batches bA=2cl, bB=2cl+1 pipelined.
// CTA rank owns 192 gate cols { g*256 + 64*rank + j } over full K=256 per batch
// (weights shared between the two batches). Warps 0-11: GEMM. Warp 12: epilogue.
__global__ __launch_bounds__(NT, 1) __cluster_dims__(CL, 1, 1)
void scan_kernel(const int* __restrict__ tokens,
                 const float* __restrict__ embed,
                 const float* __restrict__ W_ih,
                 const float* __restrict__ b_ih,
                 const float* __restrict__ W_hh,
                 const float* __restrict__ b_hh,
                 float* __restrict__ betas) {
    __shared__ float G2_s[NVv * 192];                       // gi + (bhh for r,z)
    __shared__ unsigned char tok8[2][Tt];
    __shared__ __align__(16) float part[2][3][64][4];       // [batch][gate][j][kq]
    __shared__ __align__(16) float hbuf[2][2][Hh];          // [batch][phase][256]
    __shared__ __align__(8) unsigned long long mbar[2][2];  // [batch][phase]

    const int t0   = threadIdx.x;
    const int rank = blockIdx.x & (CL - 1);
    const int cl   = blockIdx.x >> 2;
    const int bA   = 2 * cl;

    // ---- prologue
    for (int i = t0; i < 2 * Tt; i += NT) {
        int b = i >> 11, k = i & (Tt - 1);
        tok8[b][k] = (unsigned char)tokens[(bA + b) * Tt + k];
    }
    for (int i = t0; i < 2 * 2 * Hh; i += NT)
        ((float*)hbuf)[i] = 0.0f;
    if (t0 == 0) {
        #pragma unroll
        for (int b = 0; b < 2; b++)
            #pragma unroll
            for (int pp = 0; pp < 2; pp++)
                asm volatile("mbarrier.init.shared.b64 [%0], 1;"
                             :: "r"(smem_u32(&mbar[b][pp])) : "memory");
    }
    __syncthreads();

    // ---- G2 table: G2[v][c] = embed[v].W_ih[:,C] + b_ih[C] (+ b_hh[C] for r,z)
    {
        float acc[9]; int Cg[9]; int vv[9]; int ee[9];
        #pragma unroll
        for (int i = 0; i < 9; i++) {
            int e = t0 + i * NT;
            int eg = (e < NVv * 192) ? e : 0;
            int v = eg / 192, c = eg - v * 192;
            int g = c >> 6, j = c & 63;
            int C = g * 256 + rank * 64 + j;
            acc[i] = b_ih[C] + ((g < 2) ? b_hh[C] : 0.0f);
            Cg[i] = C; vv[i] = v * Hh; ee[i] = e;
        }
        for (int k = 0; k < Hh; k++) {
            const float* Wk = W_ih + (size_t)k * G3;
            #pragma unroll
            for (int i = 0; i < 9; i++)
                acc[i] = fmaf(embed[vv[i] + k], Wk[Cg[i]], acc[i]);
        }
        #pragma unroll
        for (int i = 0; i < 9; i++)
            if (ee[i] < NVv * 192) G2_s[ee[i]] = acc[i];
    }

    if (t0 < NGT) {
        // ======================= GEMM role =======================
        const int cp = t0 % 96;
        const int kq = t0 / 96;                    // warp-uniform
        const int c0 = 2 * cp;
        const int g  = c0 >> 6;
        const int j  = c0 & 63;
        const int C0 = g * 256 + rank * 64 + j;
        const int C1 = C0 + 1;

        unsigned long long w0[32], w1[32];
        {
            const float* Wb = W_hh + (size_t)(kq * 64) * G3;
            #pragma unroll
            for (int kk = 0; kk < 32; kk++) {
                w0[kk] = pack2(Wb[(2 * kk) * G3 + C0], Wb[(2 * kk + 1) * G3 + C0]);
                w1[kk] = pack2(Wb[(2 * kk) * G3 + C1], Wb[(2 * kk + 1) * G3 + C1]);
            }
        }
        // arm phases guarding h(1) and h(2) for both batches
        if (t0 == 0) {
            mbar_arm(smem_u32(&mbar[0][1]), 1024);
            mbar_arm(smem_u32(&mbar[0][0]), 1024);
            mbar_arm(smem_u32(&mbar[1][1]), 1024);
            mbar_arm(smem_u32(&mbar[1][0]), 1024);
        }
        __syncthreads();
        asm volatile("barrier.cluster.arrive.aligned;" ::: "memory");
        asm volatile("barrier.cluster.wait.aligned;"   ::: "memory");

        const unsigned mb00 = smem_u32(&mbar[0][0]);
        const unsigned mb01 = smem_u32(&mbar[0][1]);
        const unsigned mb10 = smem_u32(&mbar[1][0]);
        const unsigned mb11 = smem_u32(&mbar[1][1]);
        float* pA = &part[0][g][j][kq];
        float* pB = &part[1][g][j][kq];
        unsigned parA = 0, parB = 0;   // bit pp = parity of phase pp

        for (int t = 0; t < Tt; t++) {
            const int pc = t & 1;

            // ---- batch A
            if (t > 0) {
                const unsigned m = pc ? mb01 : mb00;
                mbar_wait(m, (parA >> pc) & 1);
                parA ^= (1u << pc);
                if (t0 == 0) mbar_arm(m, 1024);
            }
            {
                const ulonglong2* hb = (const ulonglong2*)&hbuf[0][pc][kq * 64];
                unsigned long long a0 = 0ULL, a1 = 0ULL;
                #pragma unroll
                for (int q = 0; q < 16; q++) {
                    ulonglong2 hv = hb[q];
                    a0 = fma2(w0[2 * q],     hv.x, a0);
                    a1 = fma2(w1[2 * q],     hv.x, a1);
                    a0 = fma2(w0[2 * q + 1], hv.y, a0);
                    a1 = fma2(w1[2 * q + 1], hv.y, a1);
                }
                float2 s0 = unpack2(a0), s1 = unpack2(a1);
                pA[0] = s0.x + s0.y;
                pA[4] = s1.x + s1.y;     // part[0][g][j+1][kq]
            }
            bar_arrive(1);

            // ---- batch B
            if (t > 0) {
                const unsigned m = pc ? mb11 : mb10;
                mbar_wait(m, (parB >> pc) & 1);
                parB ^= (1u << pc);
                if (t0 == 0) mbar_arm(m, 1024);
            }
            {
                const ulonglong2* hb = (const ulonglong2*)&hbuf[1][pc][kq * 64];
                unsigned long long a0 = 0ULL, a1 = 0ULL;
                #pragma unroll
                for (int q = 0; q < 16; q++) {
                    ulonglong2 hv = hb[q];
                    a0 = fma2(w0[2 * q],     hv.x, a0);
                    a1 = fma2(w1[2 * q],     hv.x, a1);
                    a0 = fma2(w0[2 * q + 1], hv.y, a0);
                    a1 = fma2(w1[2 * q + 1], hv.y, a1);
                }
                float2 s0 = unpack2(a0), s1 = unpack2(a1);
                pB[0] = s0.x + s0.y;
                pB[4] = s1.x + s1.y;
            }
            bar_arrive(2);
        }
    } else {
        // ======================= epilogue role (warp 12) =======================
        const int et   = t0 - NGT;        // 0..31
        const int j0   = 2 * et, j1 = j0 + 1;
        const int gidx = rank * 64 + j0;
        const float bhn0 = b_hh[512 + rank * 64 + j0];
        const float bhn1 = b_hh[512 + rank * 64 + j1];
        float hA0 = 0.f, hA1 = 0.f, hB0 = 0.f, hB1 = 0.f;

        __syncthreads();
        asm volatile("barrier.cluster.arrive.aligned;" ::: "memory");
        asm volatile("barrier.cluster.wait.aligned;"   ::: "memory");

        const unsigned ref = smem_u32(&hbuf[0][0][0]);
        unsigned base[CL];
        #pragma unroll
        for (int r2 = 0; r2 < CL; r2++) base[r2] = mapa_u32(ref, r2);
        unsigned hoff[2][2], moff[2][2];
        #pragma unroll
        for (int b = 0; b < 2; b++)
            #pragma unroll
            for (int pp = 0; pp < 2; pp++) {
                hoff[b][pp] = smem_u32(&hbuf[b][pp][0]) - ref;
                moff[b][pp] = smem_u32(&mbar[b][pp]) - ref;
            }
        float* obA = betas  + (size_t)bA * Tt * Hh + gidx;
        float* obB = betas  + (size_t)(bA + 1) * Tt * Hh + gidx;
        float* ohA = g_hout + (size_t)bA * Tt * Hh + gidx;
        float* ohB = g_hout + (size_t)(bA + 1) * Tt * Hh + gidx;

        for (int t = 0; t < Tt; t++) {
            const int pn = (t & 1) ^ 1;
            const int tokA = tok8[0][t];
            const int tokB = tok8[1][t];

            // ---- batch A epilogue
            bar_wait(1);
            {
                const float4 r0v = *(const float4*)&part[0][0][j0][0];
                const float4 r1v = *(const float4*)&part[0][0][j1][0];
                const float4 z0v = *(const float4*)&part[0][1][j0][0];
                const float4 z1v = *(const float4*)&part[0][1][j1][0];
                const float4 n0v = *(const float4*)&part[0][2][j0][0];
                const float4 n1v = *(const float4*)&part[0][2][j1][0];
                const float* G2 = &G2_s[tokA * 192];
                float r0 = fast_sigmoid(G2[j0] + (r0v.x + r0v.y) + (r0v.z + r0v.w));
                float r1 = fast_sigmoid(G2[j1] + (r1v.x + r1v.y) + (r1v.z + r1v.w));
                float z0 = fast_sigmoid(G2[64 + j0] + (z0v.x + z0v.y) + (z0v.z + z0v.w));
                float z1 = fast_sigmoid(G2[64 + j1] + (z1v.x + z1v.y) + (z1v.z + z1v.w));
                float sn0 = (n0v.x + n0v.y) + (n0v.z + n0v.w) + bhn0;
                float sn1 = (n1v.x + n1v.y) + (n1v.z + n1v.w) + bhn1;
                float n0 = fast_tanh(fmaf(r0, sn0, G2[128 + j0]));
                float n1 = fast_tanh(fmaf(r1, sn1, G2[128 + j1]));
                float hn0 = fmaf(z0, hA0 - n0, n0);
                float hn1 = fmaf(z1, hA1 - n1, n1);
                hA0 = hn0; hA1 = hn1;
                if (t < Tt - 1) {
                    unsigned long long pv = pack2(hn0, hn1);
                    const unsigned ho2 = hoff[0][pn] + 4u * gidx;
                    const unsigned mo2 = moff[0][pn];
                    #pragma unroll
                    for (int r2 = 0; r2 < CL; r2++)
                        asm volatile(
                            "st.async.shared::cluster.mbarrier::complete_tx::bytes.b64 [%0], %1, [%2];"
                            :: "r"(base[r2] + ho2), "l"(pv), "r"(base[r2] + mo2) : "memory");
                }
                *(float2*)(obA + (size_t)t * Hh) = make_float2(z0, z1);
                *(float2*)(ohA + (size_t)t * Hh) = make_float2(hn0, hn1);
            }

            // ---- batch B epilogue
            bar_wait(2);
            {
                const float4 r0v = *(const float4*)&part[1][0][j0][0];
                const float4 r1v = *(const float4*)&part[1][0][j1][0];
                const float4 z0v = *(const float4*)&part[1][1][j0][0];
                const float4 z1v = *(const float4*)&part[1][1][j1][0];
                const float4 n0v = *(const float4*)&part[1][2][j0][0];
                const float4 n1v = *(const float4*)&part[1][2][j1][0];
                const float* G2 = &G2_s[tokB * 192];
                float r0 = fast_sigmoid(G2[j0] + (r0v.x + r0v.y) + (r0v.z + r0v.w));
                float r1 = fast_sigmoid(G2[j1] + (r1v.x + r1v.y) + (r1v.z + r1v.w));
                float z0 = fast_sigmoid(G2[64 + j0] + (z0v.x + z0v.y) + (z0v.z + z0v.w));
                float z1 = fast_sigmoid(G2[64 + j1] + (z1v.x + z1v.y) + (z1v.z + z1v.w));
                float sn0 = (n0v.x + n0v.y) + (n0v.z + n0v.w) + bhn0;
                float sn1 = (n1v.x + n1v.y) + (n1v.z + n1v.w) + bhn1;
                float n0 = fast_tanh(fmaf(r0, sn0, G2[128 + j0]));
                float n1 = fast_tanh(fmaf(r1, sn1, G2[128 + j1]));
                float hn0 = fmaf(z0, hB0 - n0, n0);
                float hn1 = fmaf(z1, hB1 - n1, n1);
                hB0 = hn0; hB1 = hn1;
                if (t < Tt - 1) {
                    unsigned long long pv = pack2(hn0, hn1);
                    const unsigned ho2 = hoff[1][pn] + 4u * gidx;
                    const unsigned mo2 = moff[1][pn];
                    #pragma unroll
                    for (int r2 = 0; r2 < CL; r2++)
                        asm volatile(
                            "st.async.shared::cluster.mbarrier::complete_tx::bytes.b64 [%0], %1, [%2];"
                            :: "r"(base[r2] + ho2), "l"(pv), "r"(base[r2] + mo2) : "memory");
                }
                *(float2*)(obB + (size_t)t * Hh) = make_float2(z0, z1);
                *(float2*)(ohB + (size_t)t * Hh) = make_float2(hn0, hn1);
            }
        }
    }

    // all threads: no CTA may exit while peers' st.async may be in flight
    asm volatile("barrier.cluster.arrive.aligned;" ::: "memory");
    asm volatile("barrier.cluster.wait.aligned;"   ::: "memory");
}

// ---------------- kernel 2: head GEMM (4 rows/thread, broadcast LDS) ----------------
__global__ __launch_bounds__(256) void head_kernel(const float* __restrict__ W_head,
                                                   const float* __restrict__ b_head,
                                                   float* __restrict__ logits) {
    __shared__ float w_s[NOo * Hh];   // transposed: w_s[o*256 + k]
    __shared__ float b_s[NOo];
    for (int i = threadIdx.x; i < NOo * Hh; i += blockDim.x) {
        int o = i >> 8, k = i & 255;
        w_s[i] = W_head[k * NOo + o];
    }
    if (threadIdx.x < NOo) b_s[threadIdx.x] = b_head[threadIdx.x];
    __syncthreads();

    const int gid  = blockIdx.x * blockDim.x + threadIdx.x;
    const int row0 = 4 * gid;
    const float4* h0 = (const float4*)(g_hout + (size_t)row0 * Hh);
    const float4* h1 = (const float4*)(g_hout + (size_t)(row0 + 1) * Hh);
    const float4* h2 = (const float4*)(g_hout + (size_t)(row0 + 2) * Hh);
    const float4* h3 = (const float4*)(g_hout + (size_t)(row0 + 3) * Hh);

    float acc[4][NOo];
    #pragma unroll
    for (int r = 0; r < 4; r++)
        #pragma unroll
        for (int o = 0; o < NOo; o++) acc[r][o] = b_s[o];

    #pragma unroll 1
    for (int k4 = 0; k4 < Hh / 4; k4++) {
        float4 hv0 = h0[k4], hv1 = h1[k4], hv2 = h2[k4], hv3 = h3[k4];
        #pragma unroll
        for (int o = 0; o < NOo; o++) {
            const float4 wv = *(const float4*)&w_s[o * Hh + 4 * k4];
            acc[0][o] = fmaf(hv0.x, wv.x, fmaf(hv0.y, wv.y, fmaf(hv0.z, wv.z, fmaf(hv0.w, wv.w, acc[0][o]))));
            acc[1][o] = fmaf(hv1.x, wv.x, fmaf(hv1.y, wv.y, fmaf(hv1.z, wv.z, fmaf(hv1.w, wv.w, acc[1][o]))));
            acc[2][o] = fmaf(hv2.x, wv.x, fmaf(hv2.y, wv.y, fmaf(hv2.z, wv.z, fmaf(hv2.w, wv.w, acc[2][o]))));
            acc[3][o] = fmaf(hv3.x, wv.x, fmaf(hv3.y, wv.y, fmaf(hv3.z, wv.z, fmaf(hv3.w, wv.w, acc[3][o]))));
        }
    }
    #pragma unroll
    for (int r = 0; r < 4; r++) {
        float* out = logits + (size_t)(row0 + r) * NOo;
        #pragma unroll
        for (int o = 0; o < NOo; o++) out[o] = acc[r][o];
    }
}

// ---------------- launch ----------------
extern "C" void kernel_launch(void* const* d_in, const int* in_sizes, int n_in,
                              void* d_out, int out_size) {
    const int*   tokens = (const int*)d_in[0];
    const float* embed  = (const float*)d_in[1];
    const float* W_ih   = (const float*)d_in[2];
    const float* W_hh   = (const float*)d_in[3];
    const float* b_ih   = (const float*)d_in[4];
    const float* b_hh   = (const float*)d_in[5];
    const float* W_head = (const float*)d_in[6];
    const float* b_head = (const float*)d_in[7];
    (void)in_sizes; (void)n_in; (void)out_size;

    float* out    = (float*)d_out;
    float* logits = out;                          // [B*T, 17]
    float* betas  = out + (size_t)Bb * Tt * NOo;  // [B*T, 256]

    scan_kernel<<<16 * CL, NT>>>(tokens, embed, W_ih, b_ih, W_hh, b_hh, betas);
    head_kernel<<<(Bb * Tt) / 1024, 256>>>(W_head, b_head, logits);
}

// round 6
// speedup vs baseline: 1.2736x; 1.2736x over previous
#include <cuda_runtime.h>
#include <cstdint>

#define Bb   32
#define Tt   2048
#define Hh   256
#define G3   768
#define NVv  18
#define NOo  17
#define CL   4       // CTAs per cluster (one cluster per batch)
#define NT   416     // 12 FMA warps + 1 epilogue warp
#define NFT  384     // FMA threads
#define NCTA (Bb * CL)

__device__ float g_hout[Bb * Tt * Hh];

// ---------------- helpers ----------------
__device__ __forceinline__ unsigned smem_u32(const void* p) {
    return (unsigned)__cvta_generic_to_shared(p);
}
__device__ __forceinline__ unsigned mapa_u32(unsigned local, int rank) {
    unsigned r;
    asm("mapa.shared::cluster.u32 %0, %1, %2;" : "=r"(r) : "r"(local), "r"(rank));
    return r;
}
__device__ __forceinline__ unsigned long long pack2(float lo, float hi) {
    unsigned long long v;
    asm("mov.b64 %0, {%1, %2};" : "=l"(v) : "f"(lo), "f"(hi));
    return v;
}
__device__ __forceinline__ float2 unpack2(unsigned long long v) {
    float lo, hi;
    asm("mov.b64 {%0, %1}, %2;" : "=f"(lo), "=f"(hi) : "l"(v));
    return make_float2(lo, hi);
}
__device__ __forceinline__ unsigned long long fma2(unsigned long long a,
                                                   unsigned long long b,
                                                   unsigned long long c) {
    unsigned long long d;
    asm("fma.rn.f32x2 %0, %1, %2, %3;" : "=l"(d) : "l"(a), "l"(b), "l"(c));
    return d;
}
__device__ __forceinline__ float fast_sigmoid(float x) {
    float e;
    asm("ex2.approx.f32 %0, %1;" : "=f"(e) : "f"(-1.4426950408889634f * x));
    float r;
    asm("rcp.approx.f32 %0, %1;" : "=f"(r) : "f"(1.0f + e));
    return r;
}
__device__ __forceinline__ float fast_tanh(float x) {
    return fmaf(2.0f, fast_sigmoid(2.0f * x), -1.0f);
}
__device__ __forceinline__ void mbar_arm(unsigned m, unsigned bytes) {
    asm volatile("mbarrier.arrive.expect_tx.shared.b64 _, [%0], %1;"
                 :: "r"(m), "r"(bytes) : "memory");
}
__device__ __forceinline__ void mbar_wait(unsigned m, unsigned par) {
    unsigned done;
    do {
        asm volatile(
            "{\n\t.reg .pred P;\n\t"
            "mbarrier.try_wait.parity.acquire.cluster.shared::cta.b64 P, [%1], %2, 0x989680;\n\t"
            "selp.b32 %0, 1, 0, P;\n\t}"
            : "=r"(done) : "r"(m), "r"(par) : "memory");
    } while (!done);
}
__device__ __forceinline__ void bar_arrive1() {
    asm volatile("bar.arrive 1, %0;" :: "r"(NT));
}
__device__ __forceinline__ void bar_wait1() {
    asm volatile("bar.sync 1, %0;" :: "r"(NT) : "memory");
}

// ---------------- kernel 1: GRU scan ----------------
// 32 clusters x 4 CTAs, one batch per cluster. CTA rank owns 192 gate cols
// { g*256 + 64*rank + j } over full K=256 and produces h slice [64r, 64r+64).
// Warps 0-11 (FMA): thread cp=t0%96 -> col pair, kq=t0/96 -> k-quarter.
//   Per step: wait mbar[kq][pc] (slice kq of h(t)) -> FMA -> store part[pc] ->
//   bar.arrive. Quarter leader (cp==0) re-arms its mbar for t+2 after waiting.
// Warp 12 (epi): bar.sync -> reduce part -> gates -> h(t+1) -> st.async b64
//   pairs to all 4 ranks (incl self), signaling receiver's mbar[my_rank][pn].
__global__ __launch_bounds__(NT, 1) __cluster_dims__(CL, 1, 1)
void scan_kernel(const int* __restrict__ tokens,
                 const float* __restrict__ embed,
                 const float* __restrict__ W_ih,
                 const float* __restrict__ b_ih,
                 const float* __restrict__ W_hh,
                 const float* __restrict__ b_hh,
                 float* __restrict__ betas) {
    __shared__ float G2_s[NVv * 192];                       // gi (+ b_hh for r,z)
    __shared__ unsigned char tok8[Tt];
    __shared__ __align__(16) float part[2][3][64][4];       // [phase][gate][j][kq]
    __shared__ __align__(16) float hbuf[2][Hh];             // [phase][256]
    __shared__ __align__(8) unsigned long long mbar[CL][2]; // [src][phase]

    const int t0    = threadIdx.x;
    const int rank  = blockIdx.x & (CL - 1);
    const int batch = blockIdx.x >> 2;

    // ---- prologue
    for (int i = t0; i < Tt; i += NT) tok8[i] = (unsigned char)tokens[batch * Tt + i];
    for (int i = t0; i < 2 * Hh; i += NT) ((float*)hbuf)[i] = 0.0f;
    if (t0 == 0) {
        #pragma unroll
        for (int q = 0; q < CL; q++)
            #pragma unroll
            for (int pp = 0; pp < 2; pp++) {
                asm volatile("mbarrier.init.shared.b64 [%0], 1;"
                             :: "r"(smem_u32(&mbar[q][pp])) : "memory");
            }
    }
    __syncthreads();

    // ---- G2 table: G2[v][c] = embed[v].W_ih[:,C] + b_ih[C] (+ b_hh[C] for r,z)
    {
        float acc[9]; int Cg[9]; int vv[9]; int ee[9];
        #pragma unroll
        for (int i = 0; i < 9; i++) {
            int e = t0 + i * NT;
            int eg = (e < NVv * 192) ? e : 0;
            int v = eg / 192, c = eg - v * 192;
            int g = c >> 6, j = c & 63;
            int C = g * 256 + rank * 64 + j;
            acc[i] = b_ih[C] + ((g < 2) ? b_hh[C] : 0.0f);
            Cg[i] = C; vv[i] = v * Hh; ee[i] = e;
        }
        for (int k = 0; k < Hh; k++) {
            const float* Wk = W_ih + (size_t)k * G3;
            #pragma unroll
            for (int i = 0; i < 9; i++)
                acc[i] = fmaf(embed[vv[i] + k], Wk[Cg[i]], acc[i]);
        }
        #pragma unroll
        for (int i = 0; i < 9; i++)
            if (ee[i] < NVv * 192) G2_s[ee[i]] = acc[i];
    }

    if (t0 < NFT) {
        // ======================= FMA role =======================
        const int cp = t0 % 96;
        const int kq = t0 / 96;                   // warp-uniform
        const int c0 = 2 * cp;
        const int g  = c0 >> 6;
        const int j  = c0 & 63;
        const int C0 = g * 256 + rank * 64 + j;
        const int C1 = C0 + 1;

        unsigned long long w0[32], w1[32];
        {
            const float* Wb = W_hh + (size_t)(kq * 64) * G3;
            #pragma unroll
            for (int kk = 0; kk < 32; kk++) {
                w0[kk] = pack2(Wb[(2 * kk) * G3 + C0], Wb[(2 * kk + 1) * G3 + C0]);
                w1[kk] = pack2(Wb[(2 * kk) * G3 + C1], Wb[(2 * kk + 1) * G3 + C1]);
            }
        }
        // arm all 8 mbars: phase1 guards h(1), phase0 guards h(2); 256 B each
        if (t0 == 0) {
            #pragma unroll
            for (int q = 0; q < CL; q++) {
                mbar_arm(smem_u32(&mbar[q][1]), 256);
                mbar_arm(smem_u32(&mbar[q][0]), 256);
            }
        }
        __syncthreads();
        asm volatile("barrier.cluster.arrive.aligned;" ::: "memory");
        asm volatile("barrier.cluster.wait.aligned;"   ::: "memory");

        const unsigned mb0 = smem_u32(&mbar[kq][0]);
        const unsigned mb1 = smem_u32(&mbar[kq][1]);
        float* pd0 = &part[0][g][j][kq];
        float* pd1 = &part[1][g][j][kq];
        unsigned par = 0;                         // bit pp = parity of phase pp

        for (int t = 0; t < Tt; t++) {
            const int pc = t & 1;
            if (t > 0) {
                const unsigned m = pc ? mb1 : mb0;
                mbar_wait(m, (par >> pc) & 1);
                par ^= (1u << pc);
                if (cp == 0) mbar_arm(m, 256);    // quarter leader re-arms for t+2
            }
            const ulonglong2* hb = (const ulonglong2*)&hbuf[pc][kq * 64];
            unsigned long long a0 = 0ULL, a1 = 0ULL;
            #pragma unroll
            for (int q = 0; q < 16; q++) {
                ulonglong2 hv = hb[q];
                a0 = fma2(w0[2 * q],     hv.x, a0);
                a1 = fma2(w1[2 * q],     hv.x, a1);
                a0 = fma2(w0[2 * q + 1], hv.y, a0);
                a1 = fma2(w1[2 * q + 1], hv.y, a1);
            }
            float2 s0 = unpack2(a0), s1 = unpack2(a1);
            float* pd = pc ? pd1 : pd0;
            pd[0] = s0.x + s0.y;
            pd[4] = s1.x + s1.y;                  // part[pc][g][j+1][kq]
            bar_arrive1();
        }
    } else {
        // ======================= epilogue role (warp 12) =======================
        const int et   = t0 - NFT;                // 0..31
        const int j0   = 2 * et, j1 = j0 + 1;
        const int gidx = rank * 64 + j0;
        const float bhn0 = b_hh[512 + rank * 64 + j0];
        const float bhn1 = b_hh[512 + rank * 64 + j1];
        float h0 = 0.f, h1 = 0.f;

        __syncthreads();
        asm volatile("barrier.cluster.arrive.aligned;" ::: "memory");
        asm volatile("barrier.cluster.wait.aligned;"   ::: "memory");

        const unsigned ref = smem_u32(&hbuf[0][0]);
        unsigned base[CL];
        #pragma unroll
        for (int r2 = 0; r2 < CL; r2++) base[r2] = mapa_u32(ref, r2);
        unsigned hoff[2], moff[2];
        #pragma unroll
        for (int pp = 0; pp < 2; pp++) {
            hoff[pp] = smem_u32(&hbuf[pp][0]) - ref;
            moff[pp] = smem_u32(&mbar[rank][pp]) - ref;   // we are source `rank`
        }
        float* ob = betas  + (size_t)(batch * Tt) * Hh + gidx;
        float* oh = g_hout + (size_t)(batch * Tt) * Hh + gidx;

        for (int t = 0; t < Tt; t++) {
            const int pc = t & 1;
            const int pn = pc ^ 1;
            const int tok = tok8[t];

            bar_wait1();                           // all FMA partials of step t ready
            const float4 r0v = *(const float4*)&part[pc][0][j0][0];
            const float4 r1v = *(const float4*)&part[pc][0][j1][0];
            const float4 z0v = *(const float4*)&part[pc][1][j0][0];
            const float4 z1v = *(const float4*)&part[pc][1][j1][0];
            const float4 n0v = *(const float4*)&part[pc][2][j0][0];
            const float4 n1v = *(const float4*)&part[pc][2][j1][0];
            const float* G2 = &G2_s[tok * 192];
            float r0 = fast_sigmoid(G2[j0] + (r0v.x + r0v.y) + (r0v.z + r0v.w));
            float r1 = fast_sigmoid(G2[j1] + (r1v.x + r1v.y) + (r1v.z + r1v.w));
            float z0 = fast_sigmoid(G2[64 + j0] + (z0v.x + z0v.y) + (z0v.z + z0v.w));
            float z1 = fast_sigmoid(G2[64 + j1] + (z1v.x + z1v.y) + (z1v.z + z1v.w));
            float sn0 = (n0v.x + n0v.y) + (n0v.z + n0v.w) + bhn0;
            float sn1 = (n1v.x + n1v.y) + (n1v.z + n1v.w) + bhn1;
            float n0 = fast_tanh(fmaf(r0, sn0, G2[128 + j0]));
            float n1 = fast_tanh(fmaf(r1, sn1, G2[128 + j1]));
            float hn0 = fmaf(z0, h0 - n0, n0);
            float hn1 = fmaf(z1, h1 - n1, n1);
            h0 = hn0; h1 = hn1;

            if (t < Tt - 1) {
                unsigned long long pv = pack2(hn0, hn1);
                const unsigned ho2 = hoff[pn] + 4u * gidx;
                const unsigned mo2 = moff[pn];
                #pragma unroll
                for (int r2 = 0; r2 < CL; r2++)
                    asm volatile(
                        "st.async.shared::cluster.mbarrier::complete_tx::bytes.b64 [%0], %1, [%2];"
                        :: "r"(base[r2] + ho2), "l"(pv), "r"(base[r2] + mo2) : "memory");
            }
            *(float2*)(ob + (size_t)t * Hh) = make_float2(z0, z1);
            *(float2*)(oh + (size_t)t * Hh) = make_float2(hn0, hn1);
        }
    }

    // no in-flight st.async at exit (last-step sends skipped); hold cluster anyway
    asm volatile("barrier.cluster.arrive.aligned;" ::: "memory");
    asm volatile("barrier.cluster.wait.aligned;"   ::: "memory");
}

// ---------------- kernel 2: head GEMM (2 rows/thread, broadcast LDS) ----------------
__global__ __launch_bounds__(256) void head_kernel(const float* __restrict__ W_head,
                                                   const float* __restrict__ b_head,
                                                   float* __restrict__ logits) {
    __shared__ float w_s[NOo * Hh];   // transposed: w_s[o*256 + k]
    __shared__ float b_s[NOo];
    for (int i = threadIdx.x; i < NOo * Hh; i += blockDim.x) {
        int o = i >> 8, k = i & 255;
        w_s[i] = W_head[k * NOo + o];
    }
    if (threadIdx.x < NOo) b_s[threadIdx.x] = b_head[threadIdx.x];
    __syncthreads();

    const int gid = blockIdx.x * blockDim.x + threadIdx.x;
    const float4* hr0 = (const float4*)(g_hout + (size_t)(2 * gid) * Hh);
    const float4* hr1 = (const float4*)(g_hout + (size_t)(2 * gid + 1) * Hh);
    float a0[NOo], a1[NOo];
    #pragma unroll
    for (int o = 0; o < NOo; o++) { a0[o] = b_s[o]; a1[o] = b_s[o]; }
    for (int k4 = 0; k4 < Hh / 4; k4++) {
        float4 v0 = hr0[k4], v1 = hr1[k4];
        #pragma unroll
        for (int o = 0; o < NOo; o++) {
            const float4 wv = *(const float4*)&w_s[o * Hh + 4 * k4];
            a0[o] = fmaf(v0.x, wv.x, fmaf(v0.y, wv.y, fmaf(v0.z, wv.z, fmaf(v0.w, wv.w, a0[o]))));
            a1[o] = fmaf(v1.x, wv.x, fmaf(v1.y, wv.y, fmaf(v1.z, wv.z, fmaf(v1.w, wv.w, a1[o]))));
        }
    }
    float* o0 = logits + (size_t)(2 * gid) * NOo;
    float* o1 = logits + (size_t)(2 * gid + 1) * NOo;
    #pragma unroll
    for (int o = 0; o < NOo; o++) { o0[o] = a0[o]; o1[o] = a1[o]; }
}

// ---------------- launch ----------------
extern "C" void kernel_launch(void* const* d_in, const int* in_sizes, int n_in,
                              void* d_out, int out_size) {
    const int*   tokens = (const int*)d_in[0];
    const float* embed  = (const float*)d_in[1];
    const float* W_ih   = (const float*)d_in[2];
    const float* W_hh   = (const float*)d_in[3];
    const float* b_ih   = (const float*)d_in[4];
    const float* b_hh   = (const float*)d_in[5];
    const float* W_head = (const float*)d_in[6];
    const float* b_head = (const float*)d_in[7];
    (void)in_sizes; (void)n_in; (void)out_size;

    float* out    = (float*)d_out;
    float* logits = out;                          // [B*T, 17]
    float* betas  = out + (size_t)Bb * Tt * NOo;  // [B*T, 256]

    scan_kernel<<<NCTA, NT>>>(tokens, embed, W_ih, b_ih, W_hh, b_hh, betas);
    head_kernel<<<(Bb * Tt) / 512, 256>>>(W_head, b_head, logits);
}

// round 7
// speedup vs baseline: 1.5403x; 1.2094x over previous
#include <cuda_runtime.h>
#include <cstdint>

#define Bb   32
#define Tt   2048
#define Hh   256
#define G3   768
#define NVv  18
#define NOo  17
#define CL   4       // CTAs per cluster (one cluster per batch)
#define NT   384     // threads per scan CTA (all do FMA; first 64 also epi)
#define NCTA (Bb * CL)

__device__ float g_hout[Bb * Tt * Hh];

// ---------------- helpers ----------------
__device__ __forceinline__ unsigned smem_u32(const void* p) {
    return (unsigned)__cvta_generic_to_shared(p);
}
__device__ __forceinline__ unsigned mapa_u32(unsigned local, int rank) {
    unsigned r;
    asm("mapa.shared::cluster.u32 %0, %1, %2;" : "=r"(r) : "r"(local), "r"(rank));
    return r;
}
__device__ __forceinline__ unsigned long long pack2(float lo, float hi) {
    unsigned long long v;
    asm("mov.b64 %0, {%1, %2};" : "=l"(v) : "f"(lo), "f"(hi));
    return v;
}
__device__ __forceinline__ float2 unpack2(unsigned long long v) {
    float lo, hi;
    asm("mov.b64 {%0, %1}, %2;" : "=f"(lo), "=f"(hi) : "l"(v));
    return make_float2(lo, hi);
}
__device__ __forceinline__ unsigned long long fma2(unsigned long long a,
                                                   unsigned long long b,
                                                   unsigned long long c) {
    unsigned long long d;
    asm("fma.rn.f32x2 %0, %1, %2, %3;" : "=l"(d) : "l"(a), "l"(b), "l"(c));
    return d;
}
__device__ __forceinline__ float fast_sigmoid(float x) {
    float e;
    asm("ex2.approx.f32 %0, %1;" : "=f"(e) : "f"(-1.4426950408889634f * x));
    float r;
    asm("rcp.approx.f32 %0, %1;" : "=f"(r) : "f"(1.0f + e));
    return r;
}
__device__ __forceinline__ float fast_tanh(float x) {
    return fmaf(2.0f, fast_sigmoid(2.0f * x), -1.0f);
}
__device__ __forceinline__ void mbar_arm(unsigned m, unsigned bytes) {
    asm volatile("mbarrier.arrive.expect_tx.shared.b64 _, [%0], %1;"
                 :: "r"(m), "r"(bytes) : "memory");
}
__device__ __forceinline__ void mbar_wait(unsigned m, unsigned par) {
    unsigned done;
    do {
        asm volatile(
            "{\n\t.reg .pred P;\n\t"
            "mbarrier.try_wait.parity.acquire.cluster.shared::cta.b64 P, [%1], %2, 0x989680;\n\t"
            "selp.b32 %0, 1, 0, P;\n\t}"
            : "=r"(done) : "r"(m), "r"(par) : "memory");
    } while (!done);
}

// ---------------- kernel 1: GRU scan (R2 structure) ----------------
// 32 clusters x 4 CTAs, one batch per cluster. CTA rank owns 192 gate cols
// { g*256 + 64*rank + j } over full K=256 and produces h slice [64r, 64r+64).
// All 384 threads FMA (cp=t0%96 col pair, kq=t0/96 k-quarter); threads 0-63
// additionally run the inline epilogue after one __syncthreads. One mbar per
// phase; epi sends h(t+1) via st.async b32 to all 4 ranks; everyone waits.
__global__ __launch_bounds__(NT, 1) __cluster_dims__(CL, 1, 1)
void scan_kernel(const int* __restrict__ tokens,
                 const float* __restrict__ embed,
                 const float* __restrict__ W_ih,
                 const float* __restrict__ b_ih,
                 const float* __restrict__ W_hh,
                 const float* __restrict__ b_hh,
                 float* __restrict__ betas) {
    __shared__ float G2_s[NVv * 192];                 // gi + b_hh folded (r,z)
    __shared__ unsigned char tok8[Tt];
    __shared__ __align__(16) float part[4][192];      // [kq][col]
    __shared__ __align__(16) float hbuf[2][Hh];       // [phase][256]
    __shared__ __align__(8) unsigned long long mbar[2];

    const int t0    = threadIdx.x;
    const int rank  = blockIdx.x & (CL - 1);
    const int batch = blockIdx.x >> 2;
    const int cp    = t0 % 96;
    const int kq    = t0 / 96;                        // warp-uniform
    const int c0    = 2 * cp;
    const int C0    = ((c0 >> 6) << 8) + (rank << 6) + (c0 & 63);
    const int C1    = C0 + 1;

    // ---- prologue
    for (int i = t0; i < Tt; i += NT) tok8[i] = (unsigned char)tokens[batch * Tt + i];
    for (int i = t0; i < 2 * Hh; i += NT) ((float*)hbuf)[i] = 0.0f;
    if (t0 == 0) {
        asm volatile("mbarrier.init.shared.b64 [%0], 1;" :: "r"(smem_u32(&mbar[0])) : "memory");
        asm volatile("mbarrier.init.shared.b64 [%0], 1;" :: "r"(smem_u32(&mbar[1])) : "memory");
    }
    __syncthreads();

    // ---- G2 table: G2[v][c] = embed[v].W_ih[:,C] + b_ih[C] (+ b_hh[C] for r,z)
    {
        float acc[9]; int Cg[9]; int vv[9]; int ee[9];
        #pragma unroll
        for (int i = 0; i < 9; i++) {
            int e = t0 + i * NT;
            int eg = (e < NVv * 192) ? e : 0;
            int v = eg / 192, c = eg - v * 192;
            int g = c >> 6, j = c & 63;
            int C = g * 256 + rank * 64 + j;
            acc[i] = b_ih[C] + ((g < 2) ? b_hh[C] : 0.0f);
            Cg[i] = C; vv[i] = v * Hh; ee[i] = e;
        }
        for (int k = 0; k < Hh; k++) {
            const float* Wk = W_ih + (size_t)k * G3;
            #pragma unroll
            for (int i = 0; i < 9; i++)
                acc[i] = fmaf(embed[vv[i] + k], Wk[Cg[i]], acc[i]);
        }
        #pragma unroll
        for (int i = 0; i < 9; i++)
            if (ee[i] < NVv * 192) G2_s[ee[i]] = acc[i];
    }

    // ---- W_hh into registers: 2 cols x 64 k (32 f32x2 pairs each)
    unsigned long long w0[32], w1[32];
    {
        const float* Wb = W_hh + (size_t)(kq * 64) * G3;
        #pragma unroll
        for (int kk = 0; kk < 32; kk++) {
            w0[kk] = pack2(Wb[(2 * kk) * G3 + C0], Wb[(2 * kk + 1) * G3 + C0]);
            w1[kk] = pack2(Wb[(2 * kk) * G3 + C1], Wb[(2 * kk + 1) * G3 + C1]);
        }
    }
    __syncthreads();
    asm volatile("barrier.cluster.arrive.aligned;" ::: "memory");
    asm volatile("barrier.cluster.wait.aligned;"   ::: "memory");

    // ---- cluster addresses
    const unsigned ref = smem_u32(&hbuf[0][0]);
    unsigned base[CL];
    #pragma unroll
    for (int r2 = 0; r2 < CL; r2++) base[r2] = mapa_u32(ref, r2);
    unsigned hoff[2], moff[2];
    #pragma unroll
    for (int pp = 0; pp < 2; pp++) {
        hoff[pp] = smem_u32(&hbuf[pp][0]) - ref;
        moff[pp] = smem_u32(&mbar[pp]) - ref;
    }

    const unsigned mb_u32 = smem_u32(&mbar[0]);
    float* out_beta = betas  + (size_t)(batch * Tt) * Hh + (rank << 6);
    float* out_h    = g_hout + (size_t)(batch * Tt) * Hh + (rank << 6);
    const int gidx  = (rank << 6) + t0;              // valid for t0 < 64
    const float bhn = b_hh[512 + (rank << 6) + (t0 & 63)];   // n-gate bias
    float hprev = 0.0f;

    for (int t = 0; t < Tt; t++) {
        const int p = t & 1;
        if (t0 == 0) mbar_arm(mb_u32 + p * 8, 1024);

        // ---- epi prefetch (threads 0-63): token + G2 row, hidden under FMA
        const int tok = tok8[t];
        float G2r = 0.f, G2z = 0.f, G2n = 0.f;
        if (t0 < 64) {
            const float* Gr = &G2_s[tok * 192];
            G2r = Gr[t0]; G2z = Gr[64 + t0]; G2n = Gr[128 + t0];
        }

        // ---- FMA over my k-quarter (v4 broadcast loads)
        {
            const ulonglong2* hb = (const ulonglong2*)&hbuf[p][kq << 6];
            unsigned long long a0 = 0ULL, a1 = 0ULL;
            #pragma unroll
            for (int q = 0; q < 16; q++) {
                ulonglong2 hv = hb[q];
                a0 = fma2(w0[2 * q],     hv.x, a0);
                a1 = fma2(w1[2 * q],     hv.x, a1);
                a0 = fma2(w0[2 * q + 1], hv.y, a0);
                a1 = fma2(w1[2 * q + 1], hv.y, a1);
            }
            float2 s0 = unpack2(a0), s1 = unpack2(a1);
            *(float2*)&part[kq][c0] = make_float2(s0.x + s0.y, s1.x + s1.y);
        }
        __syncthreads();

        // ---- inline epilogue: threads 0-63, one h-output each
        if (t0 < 64) {
            const int j = t0;
            float sr = (part[0][j] + part[1][j]) + (part[2][j] + part[3][j]);
            float sz = (part[0][64 + j] + part[1][64 + j]) + (part[2][64 + j] + part[3][64 + j]);
            float sn = (part[0][128 + j] + part[1][128 + j]) + (part[2][128 + j] + part[3][128 + j]);
            float r  = fast_sigmoid(G2r + sr);
            float z  = fast_sigmoid(G2z + sz);
            float n  = fast_tanh(fmaf(r, sn + bhn, G2n));
            float hn = fmaf(z, hprev - n, n);        // (1-z)n + z h
            hprev = hn;

            const unsigned ho2 = hoff[p ^ 1] + 4u * gidx;
            const unsigned mo2 = moff[p];
            #pragma unroll
            for (int r2 = 0; r2 < CL; r2++) {
                asm volatile(
                    "st.async.shared::cluster.mbarrier::complete_tx::bytes.b32 [%0], %1, [%2];"
                    :: "r"(base[r2] + ho2), "f"(hn), "r"(base[r2] + mo2) : "memory");
            }
            out_beta[(size_t)t * Hh + j] = z;
            out_h[(size_t)t * Hh + j]    = hn;
        }

        // ---- all threads wait for full h(t+1) delivery
        mbar_wait(mb_u32 + p * 8, (t >> 1) & 1);
    }
}

// ---------------- kernel 2: head GEMM (2 rows/thread, broadcast LDS) ----------------
__global__ __launch_bounds__(256) void head_kernel(const float* __restrict__ W_head,
                                                   const float* __restrict__ b_head,
                                                   float* __restrict__ logits) {
    __shared__ float w_s[NOo * Hh];   // transposed: w_s[o*256 + k]
    __shared__ float b_s[NOo];
    for (int i = threadIdx.x; i < NOo * Hh; i += blockDim.x) {
        int o = i >> 8, k = i & 255;
        w_s[i] = W_head[k * NOo + o];
    }
    if (threadIdx.x < NOo) b_s[threadIdx.x] = b_head[threadIdx.x];
    __syncthreads();

    const int gid = blockIdx.x * blockDim.x + threadIdx.x;
    const float4* hr0 = (const float4*)(g_hout + (size_t)(2 * gid) * Hh);
    const float4* hr1 = (const float4*)(g_hout + (size_t)(2 * gid + 1) * Hh);
    float a0[NOo], a1[NOo];
    #pragma unroll
    for (int o = 0; o < NOo; o++) { a0[o] = b_s[o]; a1[o] = b_s[o]; }
    for (int k4 = 0; k4 < Hh / 4; k4++) {
        float4 v0 = hr0[k4], v1 = hr1[k4];
        #pragma unroll
        for (int o = 0; o < NOo; o++) {
            const float4 wv = *(const float4*)&w_s[o * Hh + 4 * k4];
            a0[o] = fmaf(v0.x, wv.x, fmaf(v0.y, wv.y, fmaf(v0.z, wv.z, fmaf(v0.w, wv.w, a0[o]))));
            a1[o] = fmaf(v1.x, wv.x, fmaf(v1.y, wv.y, fmaf(v1.z, wv.z, fmaf(v1.w, wv.w, a1[o]))));
        }
    }
    float* o0 = logits + (size_t)(2 * gid) * NOo;
    float* o1 = logits + (size_t)(2 * gid + 1) * NOo;
    #pragma unroll
    for (int o = 0; o < NOo; o++) { o0[o] = a0[o]; o1[o] = a1[o]; }
}

// ---------------- launch ----------------
extern "C" void kernel_launch(void* const* d_in, const int* in_sizes, int n_in,
                              void* d_out, int out_size) {
    const int*   tokens = (const int*)d_in[0];
    const float* embed  = (const float*)d_in[1];
    const float* W_ih   = (const float*)d_in[2];
    const float* W_hh   = (const float*)d_in[3];
    const float* b_ih   = (const float*)d_in[4];
    const float* b_hh   = (const float*)d_in[5];
    const float* W_head = (const float*)d_in[6];
    const float* b_head = (const float*)d_in[7];
    (void)in_sizes; (void)n_in; (void)out_size;

    float* out    = (float*)d_out;
    float* logits = out;                          // [B*T, 17]
    float* betas  = out + (size_t)Bb * Tt * NOo;  // [B*T, 256]

    scan_kernel<<<NCTA, NT>>>(tokens, embed, W_ih, b_ih, W_hh, b_hh, betas);
    head_kernel<<<(Bb * Tt) / 512, 256>>>(W_head, b_head, logits);
}

// round 8
// speedup vs baseline: 1.8375x; 1.1930x over previous
#include <cuda_runtime.h>
#include <cstdint>

#define Bb   32
#define Tt   2048
#define Hh   256
#define G3   768
#define NVv  18
#define NOo  17
#define CL   4       // CTAs per cluster (one cluster per batch)
#define NT   384     // threads per scan CTA
#define NCTA (Bb * CL)

// ---------------- helpers ----------------
__device__ __forceinline__ unsigned smem_u32(const void* p) {
    return (unsigned)__cvta_generic_to_shared(p);
}
__device__ __forceinline__ unsigned mapa_u32(unsigned local, int rank) {
    unsigned r;
    asm("mapa.shared::cluster.u32 %0, %1, %2;" : "=r"(r) : "r"(local), "r"(rank));
    return r;
}
__device__ __forceinline__ unsigned long long pack2(float lo, float hi) {
    unsigned long long v;
    asm("mov.b64 %0, {%1, %2};" : "=l"(v) : "f"(lo), "f"(hi));
    return v;
}
__device__ __forceinline__ float2 unpack2(unsigned long long v) {
    float lo, hi;
    asm("mov.b64 {%0, %1}, %2;" : "=f"(lo), "=f"(hi) : "l"(v));
    return make_float2(lo, hi);
}
__device__ __forceinline__ unsigned long long fma2(unsigned long long a,
                                                   unsigned long long b,
                                                   unsigned long long c) {
    unsigned long long d;
    asm("fma.rn.f32x2 %0, %1, %2, %3;" : "=l"(d) : "l"(a), "l"(b), "l"(c));
    return d;
}
__device__ __forceinline__ float fast_sigmoid(float x) {
    float e;
    asm("ex2.approx.f32 %0, %1;" : "=f"(e) : "f"(-1.4426950408889634f * x));
    float r;
    asm("rcp.approx.f32 %0, %1;" : "=f"(r) : "f"(1.0f + e));
    return r;
}
__device__ __forceinline__ float fast_tanh(float x) {
    return fmaf(2.0f, fast_sigmoid(2.0f * x), -1.0f);
}
__device__ __forceinline__ void mbar_arm(unsigned m, unsigned bytes) {
    asm volatile("mbarrier.arrive.expect_tx.shared.b64 _, [%0], %1;"
                 :: "r"(m), "r"(bytes) : "memory");
}
__device__ __forceinline__ void mbar_wait(unsigned m, unsigned par) {
    unsigned done;
    do {
        asm volatile(
            "{\n\t.reg .pred P;\n\t"
            "mbarrier.try_wait.parity.acquire.cluster.shared::cta.b64 P, [%1], %2, 0x989680;\n\t"
            "selp.b32 %0, 1, 0, P;\n\t}"
            : "=r"(done) : "r"(m), "r"(par) : "memory");
    } while (!done);
}

// ---------------- fused GRU scan + head ----------------
// 32 clusters x 4 CTAs, one batch per cluster (R2 structure). CTA rank owns
// 192 gate cols { g*256 + 64*rank + j } over full K=256; produces h slice
// [64r, 64r+64). All 384 threads FMA (cp=t0%96 col pair, kq=t0/96 k-quarter);
// threads 0-63 inline the gate epilogue; threads 320-339 compute this rank's
// share of logits[t-1] from the full h(t) already in hbuf (head GEMM fused,
// hidden in the DSMEM delivery window). One mbar per phase; st.async b32
// broadcast of h(t+1) to all 4 ranks; everyone waits at loop bottom.
__global__ __launch_bounds__(NT, 1) __cluster_dims__(CL, 1, 1)
void scan_kernel(const int* __restrict__ tokens,
                 const float* __restrict__ embed,
                 const float* __restrict__ W_ih,
                 const float* __restrict__ b_ih,
                 const float* __restrict__ W_hh,
                 const float* __restrict__ b_hh,
                 const float* __restrict__ W_head,
                 const float* __restrict__ b_head,
                 float* __restrict__ logits,
                 float* __restrict__ betas) {
    __shared__ float G2_s[NVv * 192];             // gi + b_hh folded (r,z gates)
    __shared__ float embed_s[NVv * Hh];
    __shared__ unsigned char tok8[Tt];
    __shared__ __align__(16) float part[4][192];  // [kq][col]
    __shared__ __align__(16) float hbuf[2][Hh];   // [phase][256]
    __shared__ float bhn_s[64];                   // b_hh n-gate, my 64 cols
    __shared__ __align__(16) float Wlog_s[5 * Hh];// head cols owned by this rank
    __shared__ __align__(8) unsigned long long mbar[2];

    const int t0    = threadIdx.x;
    const int rank  = blockIdx.x & (CL - 1);
    const int batch = blockIdx.x >> 2;
    const int cp    = t0 % 96;
    const int kq    = t0 / 96;                    // warp-uniform
    const int c0    = 2 * cp;
    const int C0    = ((c0 >> 6) << 8) + (rank << 6) + (c0 & 63);
    const int C1    = C0 + 1;

    // head output ownership: rank r -> { o : o%4==r, o<16 } (+ o=16 for rank 0)
    const int nout = (rank == 0) ? 5 : 4;
    const int lu   = t0 - 320;                    // logits lane (warp 10)
    const int lo   = lu >> 2;                     // local output index
    const int lk4  = lu & 3;                      // k-quarter of 256
    const bool logact = (t0 >= 320) && (t0 < 352) && (lo < nout);
    const int oo   = (lo < 4) ? (4 * lo + rank) : 16;
    const unsigned lmask = (1u << (4 * nout)) - 1u;

    // ---- prologue smem loads
    for (int i = t0; i < NVv * Hh; i += NT) embed_s[i] = embed[i];
    for (int i = t0; i < Tt; i += NT) tok8[i] = (unsigned char)tokens[batch * Tt + i];
    for (int i = t0; i < 2 * Hh; i += NT) ((float*)hbuf)[i] = 0.0f;
    if (t0 < 64) bhn_s[t0] = b_hh[512 + (rank << 6) + t0];
    for (int i = t0; i < nout * Hh; i += NT) {
        int l = i >> 8, k = i & 255;
        int o = (l < 4) ? (4 * l + rank) : 16;
        Wlog_s[i] = W_head[k * NOo + o];
    }
    if (t0 == 0) {
        asm volatile("mbarrier.init.shared.b64 [%0], 1;" :: "r"(smem_u32(&mbar[0])) : "memory");
        asm volatile("mbarrier.init.shared.b64 [%0], 1;" :: "r"(smem_u32(&mbar[1])) : "memory");
    }
    __syncthreads();

    // ---- G2 table: G2[v][c] = embed[v].W_ih[:,C] + b_ih[C] (+ b_hh[C] for r,z)
    {
        float acc[9]; int Cg[9]; int vv[9];
        #pragma unroll
        for (int i = 0; i < 9; i++) {
            int e = t0 + i * NT;
            int v = e / 192, c = e - v * 192;
            int g = c >> 6, j = c & 63;
            int C = (g << 8) + (rank << 6) + j;
            acc[i] = b_ih[C] + ((g < 2) ? b_hh[C] : 0.0f);
            Cg[i] = C; vv[i] = v * Hh;
        }
        for (int k = 0; k < Hh; k++) {
            const float* Wk = W_ih + (size_t)k * G3;
            #pragma unroll
            for (int i = 0; i < 9; i++)
                acc[i] = fmaf(embed_s[vv[i] + k], Wk[Cg[i]], acc[i]);
        }
        #pragma unroll
        for (int i = 0; i < 9; i++) {
            int e = t0 + i * NT;
            int v = e / 192, c = e - v * 192;
            G2_s[v * 192 + c] = acc[i];
        }
    }

    // ---- W_hh into registers: 2 cols x 64 k (32 f32x2 pairs each)
    unsigned long long w0[32], w1[32];
    {
        const float* Wb = W_hh + (size_t)(kq * 64) * G3;
        #pragma unroll
        for (int kk = 0; kk < 32; kk++) {
            w0[kk] = pack2(Wb[(2 * kk) * G3 + C0], Wb[(2 * kk + 1) * G3 + C0]);
            w1[kk] = pack2(Wb[(2 * kk) * G3 + C1], Wb[(2 * kk + 1) * G3 + C1]);
        }
    }
    __syncthreads();
    asm volatile("barrier.cluster.arrive.aligned;" ::: "memory");
    asm volatile("barrier.cluster.wait.aligned;"   ::: "memory");

    // ---- cluster addresses
    const unsigned ref = smem_u32(&hbuf[0][0]);
    unsigned base[CL];
    #pragma unroll
    for (int r2 = 0; r2 < CL; r2++) base[r2] = mapa_u32(ref, r2);
    unsigned hoff[2], moff[2];
    #pragma unroll
    for (int pp = 0; pp < 2; pp++) {
        hoff[pp] = smem_u32(&hbuf[pp][0]) - ref;
        moff[pp] = smem_u32(&mbar[pp]) - ref;
    }

    const unsigned mb_u32 = smem_u32(&mbar[0]);
    float* out_beta = betas + (size_t)(batch * Tt) * Hh + (rank << 6);
    float* lptr     = logits + (size_t)(batch * Tt) * NOo + oo;
    const float bh  = logact ? b_head[oo] : 0.0f;
    const int gidx  = (rank << 6) + t0;           // valid for t0 < 64
    float hprev = 0.0f;

    for (int t = 0; t < Tt; t++) {
        const int p = t & 1;
        if (t0 == 0) mbar_arm(mb_u32 + p * 8, 1024);

        // ---- FMA over my k-quarter (LDS.128 broadcast loads)
        {
            const ulonglong2* hb = (const ulonglong2*)&hbuf[p][kq << 6];
            unsigned long long a0 = 0ULL, a1 = 0ULL;
            #pragma unroll
            for (int q = 0; q < 16; q++) {
                ulonglong2 hv = hb[q];
                a0 = fma2(w0[2 * q],     hv.x, a0);
                a1 = fma2(w1[2 * q],     hv.x, a1);
                a0 = fma2(w0[2 * q + 1], hv.y, a0);
                a1 = fma2(w1[2 * q + 1], hv.y, a1);
            }
            float2 s0 = unpack2(a0), s1 = unpack2(a1);
            *(float2*)&part[kq][c0] = make_float2(s0.x + s0.y, s1.x + s1.y);
        }
        __syncthreads();

        // ---- inline gate epilogue: threads 0-63, one h-output each
        if (t0 < 64) {
            const int j = t0;
            const int tok = tok8[t];
            const float* Gr = &G2_s[tok * 192];
            float sr = (part[0][j] + part[1][j]) + (part[2][j] + part[3][j]);
            float sz = (part[0][64 + j] + part[1][64 + j]) + (part[2][64 + j] + part[3][64 + j]);
            float sn = (part[0][128 + j] + part[1][128 + j]) + (part[2][128 + j] + part[3][128 + j]);
            float r  = fast_sigmoid(Gr[j] + sr);
            float z  = fast_sigmoid(Gr[64 + j] + sz);
            float n  = fast_tanh(fmaf(r, sn + bhn_s[j], Gr[128 + j]));
            float hn = fmaf(z, hprev - n, n);      // (1-z)n + z h
            hprev = hn;

            const unsigned ho2 = hoff[p ^ 1] + 4u * gidx;
            const unsigned mo2 = moff[p];
            #pragma unroll
            for (int r2 = 0; r2 < CL; r2++) {
                asm volatile(
                    "st.async.shared::cluster.mbarrier::complete_tx::bytes.b32 [%0], %1, [%2];"
                    :: "r"(base[r2] + ho2), "f"(hn), "r"(base[r2] + mo2) : "memory");
            }
            out_beta[(size_t)t * Hh + j] = z;
        } else if (logact && t > 0) {
            // ---- fused head: logits[t-1][oo] from full h(t) in hbuf[p]
            const ulonglong2* hb = (const ulonglong2*)&hbuf[p][lk4 << 6];
            const ulonglong2* wb = (const ulonglong2*)&Wlog_s[(lo << 8) + (lk4 << 6)];
            unsigned long long a0 = 0ULL, a1 = 0ULL;
            #pragma unroll
            for (int q = 0; q < 16; q++) {
                ulonglong2 hv = hb[q];
                ulonglong2 wv = wb[q];
                a0 = fma2(wv.x, hv.x, a0);
                a1 = fma2(wv.y, hv.y, a1);
            }
            float2 s0 = unpack2(a0), s1 = unpack2(a1);
            float s = (s0.x + s0.y) + (s1.x + s1.y);
            s += __shfl_xor_sync(lmask, s, 1);
            s += __shfl_xor_sync(lmask, s, 2);
            if (lk4 == 0) lptr[(size_t)(t - 1) * NOo] = s + bh;
        }

        // ---- all threads wait for full h(t+1) delivery
        mbar_wait(mb_u32 + p * 8, (t >> 1) & 1);
    }

    // ---- final logits row (t = Tt-1): h(Tt) was delivered into hbuf[0]
    if (logact) {
        const ulonglong2* hb = (const ulonglong2*)&hbuf[0][lk4 << 6];
        const ulonglong2* wb = (const ulonglong2*)&Wlog_s[(lo << 8) + (lk4 << 6)];
        unsigned long long a0 = 0ULL, a1 = 0ULL;
        #pragma unroll
        for (int q = 0; q < 16; q++) {
            ulonglong2 hv = hb[q];
            ulonglong2 wv = wb[q];
            a0 = fma2(wv.x, hv.x, a0);
            a1 = fma2(wv.y, hv.y, a1);
        }
        float2 s0 = unpack2(a0), s1 = unpack2(a1);
        float s = (s0.x + s0.y) + (s1.x + s1.y);
        s += __shfl_xor_sync(lmask, s, 1);
        s += __shfl_xor_sync(lmask, s, 2);
        if (lk4 == 0) lptr[(size_t)(Tt - 1) * NOo] = s + bh;
    }
}

// ---------------- launch ----------------
extern "C" void kernel_launch(void* const* d_in, const int* in_sizes, int n_in,
                              void* d_out, int out_size) {
    const int*   tokens = (const int*)d_in[0];
    const float* embed  = (const float*)d_in[1];
    const float* W_ih   = (const float*)d_in[2];
    const float* W_hh   = (const float*)d_in[3];
    const float* b_ih   = (const float*)d_in[4];
    const float* b_hh   = (const float*)d_in[5];
    const float* W_head = (const float*)d_in[6];
    const float* b_head = (const float*)d_in[7];
    (void)in_sizes; (void)n_in; (void)out_size;

    float* out    = (float*)d_out;
    float* logits = out;                          // [B*T, 17]
    float* betas  = out + (size_t)Bb * Tt * NOo;  // [B*T, 256]

    scan_kernel<<<NCTA, NT>>>(tokens, embed, W_ih, b_ih, W_hh, b_hh,
                              W_head, b_head, logits, betas);
}

// round 9
// speedup vs baseline: 2.6926x; 1.4654x over previous
#include <cuda_runtime.h>
#include <cstdint>

#define Bb   32
#define Tt   2048
#define Hh   256
#define G3   768
#define NVv  18
#define NOo  17
#define CL   4       // CTAs per cluster (one cluster per batch)
#define NT   384     // threads per scan CTA
#define NCTA (Bb * CL)

__device__ float g_hout[Bb * Tt * Hh];   // h states for the head GEMM

// ---------------- helpers ----------------
__device__ __forceinline__ unsigned smem_u32(const void* p) {
    return (unsigned)__cvta_generic_to_shared(p);
}
__device__ __forceinline__ unsigned mapa_u32(unsigned local, int rank) {
    unsigned r;
    asm("mapa.shared::cluster.u32 %0, %1, %2;" : "=r"(r) : "r"(local), "r"(rank));
    return r;
}
__device__ __forceinline__ unsigned long long pack2(float lo, float hi) {
    unsigned long long v;
    asm("mov.b64 %0, {%1, %2};" : "=l"(v) : "f"(lo), "f"(hi));
    return v;
}
__device__ __forceinline__ float2 unpack2(unsigned long long v) {
    float lo, hi;
    asm("mov.b64 {%0, %1}, %2;" : "=f"(lo), "=f"(hi) : "l"(v));
    return make_float2(lo, hi);
}
__device__ __forceinline__ unsigned long long fma2(unsigned long long a,
                                                   unsigned long long b,
                                                   unsigned long long c) {
    unsigned long long d;
    asm("fma.rn.f32x2 %0, %1, %2, %3;" : "=l"(d) : "l"(a), "l"(b), "l"(c));
    return d;
}
__device__ __forceinline__ float fast_sigmoid(float x) {
    float e;
    asm("ex2.approx.f32 %0, %1;" : "=f"(e) : "f"(-1.4426950408889634f * x));
    float r;
    asm("rcp.approx.f32 %0, %1;" : "=f"(r) : "f"(1.0f + e));
    return r;
}
__device__ __forceinline__ float fast_tanh(float x) {
    return fmaf(2.0f, fast_sigmoid(2.0f * x), -1.0f);
}
__device__ __forceinline__ void mbar_arm(unsigned m, unsigned bytes) {
    asm volatile("mbarrier.arrive.expect_tx.shared.b64 _, [%0], %1;"
                 :: "r"(m), "r"(bytes) : "memory");
}
__device__ __forceinline__ void mbar_wait(unsigned m, unsigned par) {
    unsigned done;
    do {
        asm volatile(
            "{\n\t.reg .pred P;\n\t"
            "mbarrier.try_wait.parity.acquire.cluster.shared::cta.b64 P, [%1], %2, 0x989680;\n\t"
            "selp.b32 %0, 1, 0, P;\n\t}"
            : "=r"(done) : "r"(m), "r"(par) : "memory");
    } while (!done);
}

// ---------------- kernel 1: GRU scan (R2 + per-source mbars) ----------------
// 32 clusters x 4 CTAs, one batch per cluster. CTA rank owns 192 gate cols
// { g*256 + 64*rank + j } over full K=256, produces h slice [64r, 64r+64).
// All 384 threads FMA (cp=t0%96 col pair, kq=t0/96 k-quarter); threads 0-63
// inline the epilogue after one __syncthreads.
// Sends at step t: epilogue st.async h(t+1) b32 to hbuf[p^1] of all 4 ranks,
// signaling mbar[rank][p] (p = t&1, 256 B expected per source).
// Waits at top of step t (t>=1): thread waits ONLY mbar[kq][(t-1)&1] — the
// slice it multiplies — so delivery latency overlaps other slices' FMA.
__global__ __launch_bounds__(NT, 1) __cluster_dims__(CL, 1, 1)
void scan_kernel(const int* __restrict__ tokens,
                 const float* __restrict__ embed,
                 const float* __restrict__ W_ih,
                 const float* __restrict__ b_ih,
                 const float* __restrict__ W_hh,
                 const float* __restrict__ b_hh,
                 float* __restrict__ betas) {
    __shared__ float G_s[NVv * 192];
    __shared__ float embed_s[NVv * Hh];
    __shared__ int   tok_s[Tt];
    __shared__ __align__(16) float part[4][192];      // [kq][col]
    __shared__ __align__(16) unsigned long long hbuf[2][Hh / 2];  // [phase][128]
    __shared__ float bhh_s[192];
    __shared__ __align__(8) unsigned long long mbar[CL][2];       // [src][phase]

    const int t0    = threadIdx.x;
    const int rank  = blockIdx.x & (CL - 1);
    const int batch = blockIdx.x >> 2;
    const int cp    = t0 % 96;
    const int kq    = t0 / 96;                        // warp-uniform (96 = 3 warps)
    const int c0    = 2 * cp;
    const int C0    = ((c0 >> 6) << 8) + (rank << 6) + (c0 & 63);
    const int C1    = C0 + 1;

    // ---- prologue
    for (int i = t0; i < NVv * Hh; i += NT) embed_s[i] = embed[i];
    for (int i = t0; i < 192; i += NT) {
        int g = i >> 6, j = i & 63;
        bhh_s[i] = b_hh[(g << 8) + (rank << 6) + j];
    }
    for (int i = t0; i < Tt; i += NT) tok_s[i] = tokens[batch * Tt + i];
    if (t0 < Hh / 2) hbuf[0][t0] = 0ULL;              // h0 = 0
    if (t0 == 0) {
        #pragma unroll
        for (int q = 0; q < CL; q++)
            #pragma unroll
            for (int pp = 0; pp < 2; pp++)
                asm volatile("mbarrier.init.shared.b64 [%0], 1;"
                             :: "r"(smem_u32(&mbar[q][pp])) : "memory");
    }
    __syncthreads();

    // ---- G table: G[v][c] = embed[v] . W_ih[:,C] + b_ih[C]
    {
        float acc[9]; int Cg[9]; int vv[9];
        #pragma unroll
        for (int i = 0; i < 9; i++) {
            int e = t0 + i * NT;
            int v = e / 192, c = e - v * 192;
            int C = ((c >> 6) << 8) + (rank << 6) + (c & 63);
            acc[i] = b_ih[C]; Cg[i] = C; vv[i] = v * Hh;
        }
        for (int k = 0; k < Hh; k++) {
            const float* Wk = W_ih + (size_t)k * G3;
            #pragma unroll
            for (int i = 0; i < 9; i++)
                acc[i] = fmaf(embed_s[vv[i] + k], Wk[Cg[i]], acc[i]);
        }
        #pragma unroll
        for (int i = 0; i < 9; i++) {
            int e = t0 + i * NT;
            int v = e / 192, c = e - v * 192;
            G_s[v * 192 + c] = acc[i];
        }
    }

    // ---- W_hh into registers: 2 cols x 64 k (32 f32x2 pairs each)
    unsigned long long w0[32], w1[32];
    {
        const float* Wb = W_hh + (size_t)(kq * 64) * G3;
        #pragma unroll
        for (int kk = 0; kk < 32; kk++) {
            w0[kk] = pack2(Wb[(2 * kk) * G3 + C0], Wb[(2 * kk + 1) * G3 + C0]);
            w1[kk] = pack2(Wb[(2 * kk) * G3 + C1], Wb[(2 * kk + 1) * G3 + C1]);
        }
    }
    // arm both phases of all 4 source mbars (guards h(1) and h(2))
    if (t0 == 0) {
        #pragma unroll
        for (int q = 0; q < CL; q++) {
            mbar_arm(smem_u32(&mbar[q][0]), 256);
            mbar_arm(smem_u32(&mbar[q][1]), 256);
        }
    }
    __syncthreads();
    asm volatile("barrier.cluster.arrive.aligned;" ::: "memory");
    asm volatile("barrier.cluster.wait.aligned;"   ::: "memory");

    // ---- cluster addresses
    const unsigned ref = smem_u32(&hbuf[0][0]);
    unsigned base[CL];
    #pragma unroll
    for (int r2 = 0; r2 < CL; r2++) base[r2] = mapa_u32(ref, r2);
    unsigned hoff[2], moff[2];
    #pragma unroll
    for (int pp = 0; pp < 2; pp++) {
        hoff[pp] = smem_u32(&hbuf[pp][0]) - ref;
        moff[pp] = smem_u32(&mbar[rank][pp]) - ref;   // we signal as source `rank`
    }
    const unsigned mymb0 = smem_u32(&mbar[kq][0]);    // the slice I consume
    const unsigned mymb1 = smem_u32(&mbar[kq][1]);

    float* out_beta = betas  + (size_t)(batch * Tt) * Hh + (rank << 6);
    float* out_h    = g_hout + (size_t)(batch * Tt) * Hh + (rank << 6);
    const int gidx  = (rank << 6) + t0;               // valid for t0 < 64
    float hprev = 0.0f;

    for (int t = 0; t < Tt; t++) {
        const int pc = t & 1;                         // h(t) lives in hbuf[pc]

        // ---- wait only for MY slice of h(t); re-arm for t+2 (quarter leader)
        if (t > 0) {
            const int ph = (t - 1) & 1;               // mbar phase for h(t)
            const unsigned m = ph ? mymb1 : mymb0;
            mbar_wait(m, ((t - 1) >> 1) & 1);
            if (cp == 0) mbar_arm(m, 256);
        }

        // ---- FMA over my k-quarter (regs x smem-broadcast)
        {
            const unsigned long long* hb = &hbuf[pc][kq << 5];
            unsigned long long acc0 = 0ULL, acc1 = 0ULL;
            #pragma unroll
            for (int kk = 0; kk < 32; kk++) {
                unsigned long long h2 = hb[kk];
                acc0 = fma2(w0[kk], h2, acc0);
                acc1 = fma2(w1[kk], h2, acc1);
            }
            float2 a0 = unpack2(acc0), a1 = unpack2(acc1);
            *(float2*)&part[kq][c0] = make_float2(a0.x + a0.y, a1.x + a1.y);
        }
        __syncthreads();

        // ---- inline epilogue: threads 0-63, one h-output each
        if (t0 < 64) {
            const int j = t0;
            const int tok = tok_s[t];
            const float* Gr = &G_s[tok * 192];
            float sr = (part[0][j] + part[1][j]) + (part[2][j] + part[3][j]) + bhh_s[j];
            float sz = (part[0][64 + j] + part[1][64 + j]) + (part[2][64 + j] + part[3][64 + j]) + bhh_s[64 + j];
            float sn = (part[0][128 + j] + part[1][128 + j]) + (part[2][128 + j] + part[3][128 + j]) + bhh_s[128 + j];
            float r  = fast_sigmoid(Gr[j] + sr);
            float z  = fast_sigmoid(Gr[64 + j] + sz);
            float n  = fast_tanh(fmaf(r, sn, Gr[128 + j]));
            float hn = fmaf(z, hprev - n, n);         // (1-z)n + z h
            hprev = hn;

            if (t < Tt - 1) {
                const unsigned ho2 = hoff[pc ^ 1] + 4u * gidx;   // h(t+1) buffer
                const unsigned mo2 = moff[pc];                    // phase = t&1
                #pragma unroll
                for (int r2 = 0; r2 < CL; r2++) {
                    asm volatile(
                        "st.async.shared::cluster.mbarrier::complete_tx::bytes.b32 [%0], %1, [%2];"
                        :: "r"(base[r2] + ho2), "f"(hn), "r"(base[r2] + mo2) : "memory");
                }
            }
            out_beta[(size_t)t * Hh + j] = z;
            out_h[(size_t)t * Hh + j]    = hn;
        }
    }

    // nothing in flight (last-step sends skipped); hold cluster for safety
    asm volatile("barrier.cluster.arrive.aligned;" ::: "memory");
    asm volatile("barrier.cluster.wait.aligned;"   ::: "memory");
}

// ---------------- kernel 2: head GEMM (R2 original, 43 us) ----------------
__global__ __launch_bounds__(256) void head_kernel(const float* __restrict__ W_head,
                                                   const float* __restrict__ b_head,
                                                   float* __restrict__ logits) {
    __shared__ float w_s[NOo * Hh];   // transposed: w_s[o*H + k]
    __shared__ float b_s[NOo];
    for (int i = threadIdx.x; i < NOo * Hh; i += blockDim.x) {
        int o = i / Hh, k = i - o * Hh;
        w_s[i] = W_head[k * NOo + o];
    }
    if (threadIdx.x < NOo) b_s[threadIdx.x] = b_head[threadIdx.x];
    __syncthreads();

    const int row = blockIdx.x * blockDim.x + threadIdx.x;
    const float4* hr = (const float4*)(g_hout + (size_t)row * Hh);
    float acc[NOo];
    #pragma unroll
    for (int o = 0; o < NOo; o++) acc[o] = b_s[o];
    for (int k4 = 0; k4 < Hh / 4; k4++) {
        float4 hv = hr[k4];
        #pragma unroll
        for (int o = 0; o < NOo; o++) {
            const float4 wv = *(const float4*)&w_s[o * Hh + 4 * k4];
            acc[o] = fmaf(hv.x, wv.x, fmaf(hv.y, wv.y, fmaf(hv.z, wv.z, fmaf(hv.w, wv.w, acc[o]))));
        }
    }
    float* out = logits + (size_t)row * NOo;
    #pragma unroll
    for (int o = 0; o < NOo; o++) out[o] = acc[o];
}

// ---------------- launch ----------------
extern "C" void kernel_launch(void* const* d_in, const int* in_sizes, int n_in,
                              void* d_out, int out_size) {
    const int*   tokens = (const int*)d_in[0];
    const float* embed  = (const float*)d_in[1];
    const float* W_ih   = (const float*)d_in[2];
    const float* W_hh   = (const float*)d_in[3];
    const float* b_ih   = (const float*)d_in[4];
    const float* b_hh   = (const float*)d_in[5];
    const float* W_head = (const float*)d_in[6];
    const float* b_head = (const float*)d_in[7];
    (void)in_sizes; (void)n_in; (void)out_size;

    float* out    = (float*)d_out;
    float* logits = out;                          // [B*T, 17]
    float* betas  = out + (size_t)Bb * Tt * NOo;  // [B*T, 256]

    scan_kernel<<<NCTA, NT>>>(tokens, embed, W_ih, b_ih, W_hh, b_hh, betas);
    head_kernel<<<(Bb * Tt) / 256, 256>>>(W_head, b_head, logits);
}